// round 10
// baseline (speedup 1.0000x reference)
#include <cuda_runtime.h>
#include <cuda_bf16.h>
#include <cstdint>

// Problem constants
#define NUM_NODES 50000
#define NUM_EDGES 800000
#define D_IN  128
#define D_HID 128
#define D_OUT 40

#define SCAN_BLK 512
#define SCAN_NBLOCKS ((NUM_NODES + SCAN_BLK - 1) / SCAN_BLK)   // 98

// Padded bf16 tile row stride (bytes): 128 cols * 2B + 16B pad = 272
// (68 words; 8 consecutive rows hit banks 0,4,...,28 -> ldmatrix conflict-free)
#define TPAD 272
#define W_TILE_BYTES (128 * TPAD)          // 34816
#define A_TILE_BYTES (64 * TPAD)           // 17408

// Scratch buffers (device globals; no allocation allowed)
__device__ float g_bufHW[NUM_NODES * D_HID];   // projected features h@W
__device__ float g_bufAGG[NUM_NODES * D_HID];  // aggregation target
__device__ int   g_is64;                       // edge_index dtype flag
__device__ int   g_deg[NUM_NODES];             // degree counts, then fill cursor
__device__ int   g_off[NUM_NODES + 1];         // CSR row offsets (by dst)
__device__ int   g_csrc[NUM_EDGES];            // CSR source ids
__device__ int   g_bsum[SCAN_NBLOCKS];         // per-block scan partials

// Pre-split W blobs, [n][k] layout, padded rows (2176 uint4 = 34816 B each)
__device__ uint4 g_W0hi[2176];
__device__ uint4 g_W0lo[2176];
__device__ uint4 g_W1hi[2176];
__device__ uint4 g_W1lo[2176];

// ---------------------------------------------------------------------------
// f32x2 packed-FMA helpers (for the small 40-dim GEMM)
// ---------------------------------------------------------------------------
__device__ __forceinline__ unsigned long long pack2(float x, float y) {
    unsigned long long r;
    asm("mov.b64 %0, {%1, %2};" : "=l"(r) : "f"(x), "f"(y));
    return r;
}
#define FMA2(d, a, b) \
    asm("fma.rn.f32x2 %0, %1, %2, %0;" : "+l"(d) : "l"(a), "l"(b))

// ---------------------------------------------------------------------------
// mma.sync / ldmatrix helpers (baseline PTX — works on plain sm_103 target)
// ---------------------------------------------------------------------------
__device__ __forceinline__ uint32_t smem_u32(const void* p) {
    uint32_t a;
    asm("{ .reg .u64 t; cvta.to.shared.u64 t, %1; cvt.u32.u64 %0, t; }"
        : "=r"(a) : "l"(p));
    return a;
}

#define LDSM_X4(r, addr)                                                      \
    asm volatile("ldmatrix.sync.aligned.m8n8.x4.shared.b16 {%0,%1,%2,%3}, [%4];" \
        : "=r"((r)[0]), "=r"((r)[1]), "=r"((r)[2]), "=r"((r)[3])              \
        : "r"(addr))

__device__ __forceinline__ void mma16816(float* c, const uint32_t* a,
                                         uint32_t b0, uint32_t b1) {
    asm volatile(
        "mma.sync.aligned.m16n8k16.row.col.f32.bf16.bf16.f32 "
        "{%0,%1,%2,%3}, {%4,%5,%6,%7}, {%8,%9}, {%0,%1,%2,%3};"
        : "+f"(c[0]), "+f"(c[1]), "+f"(c[2]), "+f"(c[3])
        : "r"(a[0]), "r"(a[1]), "r"(a[2]), "r"(a[3]), "r"(b0), "r"(b1));
}

// split fp32 pair -> (hi bf16x2, lo bf16x2)
__device__ __forceinline__ void split2(float a, float b, uint32_t& hi, uint32_t& lo) {
    __nv_bfloat16 ha = __float2bfloat16(a), hb = __float2bfloat16(b);
    float ra = a - __bfloat162float(ha);
    float rb = b - __bfloat162float(hb);
    __nv_bfloat16 la = __float2bfloat16(ra), lb = __float2bfloat16(rb);
    hi = ((uint32_t)__bfloat16_as_ushort(hb) << 16) | __bfloat16_as_ushort(ha);
    lo = ((uint32_t)__bfloat16_as_ushort(lb) << 16) | __bfloat16_as_ushort(la);
}

// ---------------------------------------------------------------------------
// Detect whether edge_index is int64 (odd 32-bit words all zero) or int32.
// ---------------------------------------------------------------------------
__global__ void detect_idx_dtype(const int* __restrict__ ei32) {
    if (threadIdx.x == 0 && blockIdx.x == 0) {
        int is64 = 1;
        for (int i = 0; i < 256; i++) {
            if (ei32[2 * i + 1] != 0) { is64 = 0; break; }
        }
        g_is64 = is64;
    }
}

// ---------------------------------------------------------------------------
// W prep: split W0/W1 into bf16 hi/lo, transposed to [n][k], padded rows.
// 256 threads: t<128 -> W0 col n=t ; t>=128 -> W1 col n=t-128.
// ---------------------------------------------------------------------------
__global__ void prep_w_kernel(const float* __restrict__ W0,
                              const float* __restrict__ W1) {
    int t = threadIdx.x;
    const float* W = (t < 128) ? W0 : W1;
    char* hi = (char*)((t < 128) ? g_W0hi : g_W1hi);
    char* lo = (char*)((t < 128) ? g_W0lo : g_W1lo);
    int n = t & 127;
    for (int k = 0; k < 128; k += 2) {
        float v0 = W[(size_t)k * 128 + n];
        float v1 = W[(size_t)(k + 1) * 128 + n];
        uint32_t h, l;
        split2(v0, v1, h, l);
        uint32_t off = (uint32_t)n * TPAD + k * 2;
        *(uint32_t*)(hi + off) = h;
        *(uint32_t*)(lo + off) = l;
    }
}

// ---------------------------------------------------------------------------
// CSR build: zero (memset) -> histogram(dst) -> 3-phase scan -> fill
// ---------------------------------------------------------------------------
__global__ void hist_kernel(const int* __restrict__ ei32, int E) {
    int e = blockIdx.x * blockDim.x + threadIdx.x;
    if (e >= E) return;
    int d = g_is64 ? ei32[2 * (E + e)] : ei32[E + e];
    atomicAdd(&g_deg[d], 1);
}

__global__ void scanA_kernel() {
    __shared__ int wsum[16];
    const int tid = threadIdx.x;
    const int lane = tid & 31, wid = tid >> 5;
    int i = blockIdx.x * SCAN_BLK + tid;
    int v = (i < NUM_NODES) ? g_deg[i] : 0;
    int x = v;
    #pragma unroll
    for (int s = 1; s < 32; s <<= 1) {
        int t = __shfl_up_sync(0xffffffffu, x, s);
        if (lane >= s) x += t;
    }
    if (lane == 31) wsum[wid] = x;
    __syncthreads();
    if (wid == 0 && lane < 16) {
        int y = wsum[lane];
        #pragma unroll
        for (int s = 1; s < 16; s <<= 1) {
            int t = __shfl_up_sync(0xffffu, y, s);
            if (lane >= s) y += t;
        }
        wsum[lane] = y;
    }
    __syncthreads();
    int warpoff = (wid == 0) ? 0 : wsum[wid - 1];
    if (i < NUM_NODES) g_off[i] = warpoff + x - v;
    if (tid == SCAN_BLK - 1) g_bsum[blockIdx.x] = wsum[15];
}

__global__ void scanB_kernel() {
    __shared__ int wsum[4];
    const int tid = threadIdx.x;     // 128 threads
    const int lane = tid & 31, wid = tid >> 5;
    int v = (tid < SCAN_NBLOCKS) ? g_bsum[tid] : 0;
    int x = v;
    #pragma unroll
    for (int s = 1; s < 32; s <<= 1) {
        int t = __shfl_up_sync(0xffffffffu, x, s);
        if (lane >= s) x += t;
    }
    if (lane == 31) wsum[wid] = x;
    __syncthreads();
    if (tid == 0) {
        int c = 0;
        #pragma unroll
        for (int k = 0; k < 4; k++) { int t = wsum[k]; wsum[k] = c; c += t; }
    }
    __syncthreads();
    int excl = wsum[wid] + x - v;
    if (tid < SCAN_NBLOCKS) g_bsum[tid] = excl;
    if (tid == 127) g_off[NUM_NODES] = excl + v;     // grand total (=E)
}

__global__ void scanC_kernel() {
    int i = blockIdx.x * blockDim.x + threadIdx.x;
    if (i >= NUM_NODES) return;
    int o = g_off[i] + g_bsum[i / SCAN_BLK];
    g_off[i] = o;
    g_deg[i] = o;
}

__global__ void fill_kernel(const int* __restrict__ ei32, int E) {
    int e = blockIdx.x * blockDim.x + threadIdx.x;
    if (e >= E) return;
    int s, d;
    if (g_is64) { s = ei32[2 * e]; d = ei32[2 * (E + e)]; }
    else        { s = ei32[e];     d = ei32[E + e]; }
    int pos = atomicAdd(&g_deg[d], 1);
    g_csrc[pos] = s;
}

// ---------------------------------------------------------------------------
// Tensor-core GEMM via mma.sync: C[N,128] = act(A[N,128]) @ W[128,128]
// Split-bf16, 3 terms: ah*wh + ah*wl + al*wh.  Block = 64 rows x 128 cols,
// 8 warps = 4 row-bands(16) x 2 col-halves(64). SMEM: Ahi/Alo + Whi/Wlo.
// ---------------------------------------------------------------------------
#define SM_AHI 0
#define SM_ALO (SM_AHI + A_TILE_BYTES)
#define SM_WHI (SM_ALO + A_TILE_BYTES)
#define SM_WLO (SM_WHI + W_TILE_BYTES)
#define SM_TC_TOTAL (SM_WLO + W_TILE_BYTES)    // 104448 B

template <bool RELU>
__global__ __launch_bounds__(256, 2)
void gemm128_tc_kernel(const float* __restrict__ A,
                       const uint4* __restrict__ Whi,
                       const uint4* __restrict__ Wlo,
                       float* __restrict__ C, int N) {
    extern __shared__ char smem[];
    const uint32_t sbase = smem_u32(smem);
    const int tid = threadIdx.x;
    const int wid = tid >> 5;
    const int lane = tid & 31;

    // Copy W hi/lo blobs (2176 uint4 each = 4352 total, 17 per thread)
    {
        uint4* whs = (uint4*)(smem + SM_WHI);
        uint4* wls = (uint4*)(smem + SM_WLO);
        #pragma unroll
        for (int i = 0; i < 8; i++) whs[tid + i * 256] = Whi[tid + i * 256];
        #pragma unroll
        for (int i = 0; i < 8; i++) wls[tid + i * 256] = Wlo[tid + i * 256];
        int idx = tid + 2048;
        if (idx < 2176) { whs[idx] = Whi[idx]; wls[idx] = Wlo[idx]; }
    }

    // Load + split A tile: thread t -> row t>>2, k-quarter (t&3)*32
    const int rowBase = blockIdx.x * 64;
    {
        int r = tid >> 2;
        int kbase = (tid & 3) * 32;
        int grow = rowBase + r;
        char* ahs = smem + SM_AHI + (uint32_t)r * TPAD;
        char* als = smem + SM_ALO + (uint32_t)r * TPAD;
        if (grow < N) {
            const float4* Ar = (const float4*)(A + (size_t)grow * 128 + kbase);
            #pragma unroll
            for (int j = 0; j < 8; j++) {
                float4 v = Ar[j];
                if (RELU) {
                    v.x = fmaxf(v.x, 0.f); v.y = fmaxf(v.y, 0.f);
                    v.z = fmaxf(v.z, 0.f); v.w = fmaxf(v.w, 0.f);
                }
                int k0 = kbase + j * 4;
                uint32_t h0, l0, h1, l1;
                split2(v.x, v.y, h0, l0);
                split2(v.z, v.w, h1, l1);
                *(uint32_t*)(ahs + k0 * 2)     = h0;
                *(uint32_t*)(als + k0 * 2)     = l0;
                *(uint32_t*)(ahs + k0 * 2 + 4) = h1;
                *(uint32_t*)(als + k0 * 2 + 4) = l1;
            }
        } else {
            #pragma unroll
            for (int j = 0; j < 8; j++) {
                int k0 = kbase + j * 4;
                *(uint64_t*)(ahs + k0 * 2) = 0ull;
                *(uint64_t*)(als + k0 * 2) = 0ull;
            }
        }
    }
    __syncthreads();

    const int wr = (wid & 3) * 16;    // warp row band
    const int wc = (wid >> 2) * 64;   // warp col half

    float acc[8][4];
    #pragma unroll
    for (int t = 0; t < 8; t++)
        #pragma unroll
        for (int c = 0; c < 4; c++) acc[t][c] = 0.f;

    // ldmatrix lane addressing: row = lane%16, 16B chunk = lane/16
    const uint32_t aoffs = (uint32_t)(wr + (lane & 15)) * TPAD + (lane >> 4) * 16;
    const uint32_t ahiAddr = sbase + SM_AHI + aoffs;
    const uint32_t aloAddr = sbase + SM_ALO + aoffs;

    #pragma unroll
    for (int ks = 0; ks < 8; ks++) {
        const uint32_t kb = ks * 32;   // byte offset of k-step (16 bf16)
        uint32_t ah[4], al[4];
        LDSM_X4(ah, ahiAddr + kb);
        LDSM_X4(al, aloAddr + kb);

        #pragma unroll
        for (int g = 0; g < 4; g++) {  // 4 n16-groups per warp
            uint32_t baddr = sbase + SM_WHI +
                (uint32_t)(wc + g * 16 + (lane & 15)) * TPAD + (lane >> 4) * 16 + kb;
            uint32_t bh[4], bl[4];
            LDSM_X4(bh, baddr);
            LDSM_X4(bl, baddr + W_TILE_BYTES);
            #pragma unroll
            for (int h = 0; h < 2; h++) {
                int t = g * 2 + h;
                mma16816(acc[t], ah, bh[h], bh[h + 2]);
                mma16816(acc[t], ah, bl[h], bl[h + 2]);
                mma16816(acc[t], al, bh[h], bh[h + 2]);
            }
        }
    }

    // Epilogue: c0,c1 -> row lane/4 ; c2,c3 -> row lane/4 + 8
    {
        int r0 = rowBase + wr + (lane >> 2);
        int r1 = r0 + 8;
        #pragma unroll
        for (int t = 0; t < 8; t++) {
            int col = wc + t * 8 + (lane & 3) * 2;
            if (r0 < N)
                *(float2*)(C + (size_t)r0 * 128 + col) = make_float2(acc[t][0], acc[t][1]);
            if (r1 < N)
                *(float2*)(C + (size_t)r1 * 128 + col) = make_float2(acc[t][2], acc[t][3]);
        }
    }
}

// ---------------------------------------------------------------------------
// GEMM: C[N,40] = relu(A[N,128]) @ W[128,40] — f32x2, one row per thread.
// ---------------------------------------------------------------------------
__global__ void gemm40_kernel(const float* __restrict__ A, const float* __restrict__ W,
                              float* __restrict__ C, int N) {
    __shared__ float Ws[128 * 40];
    for (int i = threadIdx.x; i < 128 * 40; i += blockDim.x) Ws[i] = W[i];
    __syncthreads();

    int row = blockIdx.x * blockDim.x + threadIdx.x;
    if (row >= N) return;

    unsigned long long acc2[20];
    #pragma unroll
    for (int j = 0; j < 20; j++) acc2[j] = 0ull;

    const float4* Arow = (const float4*)(A + (size_t)row * 128);
    for (int k4 = 0; k4 < 32; k4++) {
        float4 a = Arow[k4];
        a.x = fmaxf(a.x, 0.f); a.y = fmaxf(a.y, 0.f);
        a.z = fmaxf(a.z, 0.f); a.w = fmaxf(a.w, 0.f);
        #pragma unroll
        for (int kk = 0; kk < 4; kk++) {
            float av = (kk == 0) ? a.x : (kk == 1) ? a.y : (kk == 2) ? a.z : a.w;
            unsigned long long av2 = pack2(av, av);
            const unsigned long long* wrow =
                (const unsigned long long*)(Ws + (k4 * 4 + kk) * 40);
            #pragma unroll
            for (int j = 0; j < 20; j++) FMA2(acc2[j], av2, wrow[j]);
        }
    }

    unsigned long long* Co = (unsigned long long*)(C + (size_t)row * 40);
    #pragma unroll
    for (int j = 0; j < 20; j++) Co[j] = acc2[j];
}

// ---------------------------------------------------------------------------
// CSR gather (128 dims): one warp per node, lane owns 4 cols.
// ---------------------------------------------------------------------------
__global__ void gather128_kernel(const float* __restrict__ hw,
                                 const float* __restrict__ b,
                                 float* __restrict__ agg) {
    int w = (blockIdx.x * blockDim.x + threadIdx.x) >> 5;
    int lane = threadIdx.x & 31;
    if (w >= NUM_NODES) return;
    int beg = __ldg(&g_off[w]);
    int end = __ldg(&g_off[w + 1]);

    float4 acc = *(const float4*)(b + lane * 4);
    int i = beg;
    for (; i + 4 <= end; i += 4) {
        int s0 = g_csrc[i], s1 = g_csrc[i + 1], s2 = g_csrc[i + 2], s3 = g_csrc[i + 3];
        float4 v0 = *(const float4*)(hw + (size_t)s0 * 128 + lane * 4);
        float4 v1 = *(const float4*)(hw + (size_t)s1 * 128 + lane * 4);
        float4 v2 = *(const float4*)(hw + (size_t)s2 * 128 + lane * 4);
        float4 v3 = *(const float4*)(hw + (size_t)s3 * 128 + lane * 4);
        acc.x += v0.x + v1.x + v2.x + v3.x;
        acc.y += v0.y + v1.y + v2.y + v3.y;
        acc.z += v0.z + v1.z + v2.z + v3.z;
        acc.w += v0.w + v1.w + v2.w + v3.w;
    }
    for (; i < end; i++) {
        int s = g_csrc[i];
        float4 v = *(const float4*)(hw + (size_t)s * 128 + lane * 4);
        acc.x += v.x; acc.y += v.y; acc.z += v.z; acc.w += v.w;
    }
    *(float4*)(agg + (size_t)w * 128 + lane * 4) = acc;
}

// ---------------------------------------------------------------------------
// CSR gather (40 dims): one warp per node, lanes 0..9 own a float4 each.
// ---------------------------------------------------------------------------
__global__ void gather40_kernel(const float* __restrict__ hw,
                                const float* __restrict__ b,
                                float* __restrict__ out) {
    int w = (blockIdx.x * blockDim.x + threadIdx.x) >> 5;
    int lane = threadIdx.x & 31;
    if (w >= NUM_NODES) return;
    int beg = __ldg(&g_off[w]);
    int end = __ldg(&g_off[w + 1]);

    float4 acc = make_float4(0.f, 0.f, 0.f, 0.f);
    if (lane < 10) acc = *(const float4*)(b + lane * 4);
    int i = beg;
    for (; i + 2 <= end; i += 2) {
        int s0 = g_csrc[i], s1 = g_csrc[i + 1];
        if (lane < 10) {
            float4 v0 = *(const float4*)(hw + (size_t)s0 * 40 + lane * 4);
            float4 v1 = *(const float4*)(hw + (size_t)s1 * 40 + lane * 4);
            acc.x += v0.x + v1.x; acc.y += v0.y + v1.y;
            acc.z += v0.z + v1.z; acc.w += v0.w + v1.w;
        }
    }
    for (; i < end; i++) {
        int s = g_csrc[i];
        if (lane < 10) {
            float4 v = *(const float4*)(hw + (size_t)s * 40 + lane * 4);
            acc.x += v.x; acc.y += v.y; acc.z += v.z; acc.w += v.w;
        }
    }
    if (lane < 10)
        *(float4*)(out + (size_t)w * 40 + lane * 4) = acc;
}

// ---------------------------------------------------------------------------
// Launch — CSR build on side stream; W prep + HMMA GEMMs on main.
// ---------------------------------------------------------------------------
extern "C" void kernel_launch(void* const* d_in, const int* in_sizes, int n_in,
                              void* d_out, int out_size) {
    const float* x  = (const float*)d_in[0];
    const int*   ei = (const int*)d_in[1];
    const float* W0 = (const float*)d_in[2];
    const float* b0 = (const float*)d_in[3];
    const float* W1 = (const float*)d_in[4];
    const float* b1 = (const float*)d_in[5];
    const float* W2 = (const float*)d_in[6];
    const float* b2 = (const float*)d_in[7];
    float* out = (float*)d_out;

    const int N = NUM_NODES, E = NUM_EDGES;

    float *bufHW, *bufAGG;
    cudaGetSymbolAddress((void**)&bufHW, g_bufHW);
    cudaGetSymbolAddress((void**)&bufAGG, g_bufAGG);
    int* degPtr;
    cudaGetSymbolAddress((void**)&degPtr, g_deg);
    uint4 *w0hi, *w0lo, *w1hi, *w1lo;
    cudaGetSymbolAddress((void**)&w0hi, g_W0hi);
    cudaGetSymbolAddress((void**)&w0lo, g_W0lo);
    cudaGetSymbolAddress((void**)&w1hi, g_W1hi);
    cudaGetSymbolAddress((void**)&w1lo, g_W1lo);

    cudaFuncSetAttribute(gemm128_tc_kernel<false>,
                         cudaFuncAttributeMaxDynamicSharedMemorySize, SM_TC_TOTAL);
    cudaFuncSetAttribute(gemm128_tc_kernel<true>,
                         cudaFuncAttributeMaxDynamicSharedMemorySize, SM_TC_TOTAL);

    static cudaStream_t sideStream = nullptr;
    static cudaEvent_t evFork = nullptr, evJoin = nullptr;
    if (sideStream == nullptr) {
        cudaStreamCreateWithFlags(&sideStream, cudaStreamNonBlocking);
        cudaEventCreateWithFlags(&evFork, cudaEventDisableTiming);
        cudaEventCreateWithFlags(&evJoin, cudaEventDisableTiming);
    }

    // --- fork: CSR build on side stream ---
    cudaEventRecord(evFork, 0);
    cudaStreamWaitEvent(sideStream, evFork, 0);

    detect_idx_dtype<<<1, 32, 0, sideStream>>>(ei);
    cudaMemsetAsync(degPtr, 0, NUM_NODES * sizeof(int), sideStream);
    hist_kernel<<<(E + 255) / 256, 256, 0, sideStream>>>(ei, E);
    scanA_kernel<<<SCAN_NBLOCKS, SCAN_BLK, 0, sideStream>>>();
    scanB_kernel<<<1, 128, 0, sideStream>>>();
    scanC_kernel<<<(N + 255) / 256, 256, 0, sideStream>>>();
    fill_kernel<<<(E + 255) / 256, 256, 0, sideStream>>>(ei, E);
    cudaEventRecord(evJoin, sideStream);

    // --- main stream: W prep + layer-0 GEMM (only need x, W0, W1) ---
    const int GEMM_BLOCKS = (N + 63) / 64;   // 782
    prep_w_kernel<<<1, 256>>>(W0, W1);
    gemm128_tc_kernel<false><<<GEMM_BLOCKS, 256, SM_TC_TOTAL>>>(x, w0hi, w0lo, bufHW, N);

    // --- join: gather needs CSR + layer-0 projections ---
    cudaStreamWaitEvent(0, evJoin, 0);

    const int GWARP_BLOCKS = (N * 32 + 255) / 256;  // 1 warp per node

    gather128_kernel<<<GWARP_BLOCKS, 256>>>(bufHW, b0, bufAGG);

    // Layer 1
    gemm128_tc_kernel<true><<<GEMM_BLOCKS, 256, SM_TC_TOTAL>>>(bufAGG, w1hi, w1lo, bufHW, N);
    gather128_kernel<<<GWARP_BLOCKS, 256>>>(bufHW, b1, bufAGG);

    // Layer 2
    gemm40_kernel<<<(N + 255) / 256, 256>>>(bufAGG, W2, bufHW, N);
    gather40_kernel<<<GWARP_BLOCKS, 256>>>(bufHW, b2, out);
}

// round 11
// speedup vs baseline: 1.2537x; 1.2537x over previous
#include <cuda_runtime.h>
#include <cuda_bf16.h>
#include <cstdint>

// Problem constants
#define NUM_NODES 50000
#define NUM_EDGES 800000
#define D_IN  128
#define D_HID 128
#define D_OUT 40
#define HALF0 25000
#define HALF1 (NUM_NODES - HALF0)

#define SCAN_BLK 512
#define SCAN_NBLOCKS ((NUM_NODES + SCAN_BLK - 1) / SCAN_BLK)   // 98

// Scratch buffers (device globals; no allocation allowed)
__device__ float g_bufHW[NUM_NODES * D_HID];   // projected features h@W
__device__ float g_bufAGG[NUM_NODES * D_HID];  // aggregation target
__device__ int   g_is64;                       // edge_index dtype flag
__device__ int   g_deg[NUM_NODES];             // degree counts, then fill cursor
__device__ int   g_off[NUM_NODES + 1];         // CSR row offsets (by dst)
__device__ int   g_csrc[NUM_EDGES];            // CSR source ids
__device__ int   g_bsum[SCAN_NBLOCKS];         // per-block scan partials

// ---------------------------------------------------------------------------
// f32x2 packed-FMA helpers (Blackwell dual-FP32 pipe, PTX-only)
// ---------------------------------------------------------------------------
__device__ __forceinline__ unsigned long long pack2(float x, float y) {
    unsigned long long r;
    asm("mov.b64 %0, {%1, %2};" : "=l"(r) : "f"(x), "f"(y));
    return r;
}
__device__ __forceinline__ void unpack2(float& x, float& y, unsigned long long v) {
    asm("mov.b64 {%0, %1}, %2;" : "=f"(x), "=f"(y) : "l"(v));
}
#define FMA2(d, a, b) \
    asm("fma.rn.f32x2 %0, %1, %2, %0;" : "+l"(d) : "l"(a), "l"(b))

// ---------------------------------------------------------------------------
// Detect whether edge_index is int64 (odd 32-bit words all zero) or int32.
// ---------------------------------------------------------------------------
__global__ void detect_idx_dtype(const int* __restrict__ ei32) {
    if (threadIdx.x == 0 && blockIdx.x == 0) {
        int is64 = 1;
        for (int i = 0; i < 256; i++) {
            if (ei32[2 * i + 1] != 0) { is64 = 0; break; }
        }
        g_is64 = is64;
    }
}

// ---------------------------------------------------------------------------
// CSR build: zero (memset) -> histogram(dst) -> 3-phase scan -> fill
// ---------------------------------------------------------------------------
__global__ void hist_kernel(const int* __restrict__ ei32, int E) {
    int e = blockIdx.x * blockDim.x + threadIdx.x;
    if (e >= E) return;
    int d = g_is64 ? ei32[2 * (E + e)] : ei32[E + e];
    atomicAdd(&g_deg[d], 1);
}

__global__ void scanA_kernel() {
    __shared__ int wsum[16];
    const int tid = threadIdx.x;
    const int lane = tid & 31, wid = tid >> 5;
    int i = blockIdx.x * SCAN_BLK + tid;
    int v = (i < NUM_NODES) ? g_deg[i] : 0;
    int x = v;
    #pragma unroll
    for (int s = 1; s < 32; s <<= 1) {
        int t = __shfl_up_sync(0xffffffffu, x, s);
        if (lane >= s) x += t;
    }
    if (lane == 31) wsum[wid] = x;
    __syncthreads();
    if (wid == 0 && lane < 16) {
        int y = wsum[lane];
        #pragma unroll
        for (int s = 1; s < 16; s <<= 1) {
            int t = __shfl_up_sync(0xffffu, y, s);
            if (lane >= s) y += t;
        }
        wsum[lane] = y;
    }
    __syncthreads();
    int warpoff = (wid == 0) ? 0 : wsum[wid - 1];
    if (i < NUM_NODES) g_off[i] = warpoff + x - v;
    if (tid == SCAN_BLK - 1) g_bsum[blockIdx.x] = wsum[15];
}

__global__ void scanB_kernel() {
    __shared__ int wsum[4];
    const int tid = threadIdx.x;     // 128 threads
    const int lane = tid & 31, wid = tid >> 5;
    int v = (tid < SCAN_NBLOCKS) ? g_bsum[tid] : 0;
    int x = v;
    #pragma unroll
    for (int s = 1; s < 32; s <<= 1) {
        int t = __shfl_up_sync(0xffffffffu, x, s);
        if (lane >= s) x += t;
    }
    if (lane == 31) wsum[wid] = x;
    __syncthreads();
    if (tid == 0) {
        int c = 0;
        #pragma unroll
        for (int k = 0; k < 4; k++) { int t = wsum[k]; wsum[k] = c; c += t; }
    }
    __syncthreads();
    int excl = wsum[wid] + x - v;
    if (tid < SCAN_NBLOCKS) g_bsum[tid] = excl;
    if (tid == 127) g_off[NUM_NODES] = excl + v;     // grand total (=E)
}

__global__ void scanC_kernel() {
    int i = blockIdx.x * blockDim.x + threadIdx.x;
    if (i >= NUM_NODES) return;
    int o = g_off[i] + g_bsum[i / SCAN_BLK];
    g_off[i] = o;
    g_deg[i] = o;
}

__global__ void fill_kernel(const int* __restrict__ ei32, int E) {
    int e = blockIdx.x * blockDim.x + threadIdx.x;
    if (e >= E) return;
    int s, d;
    if (g_is64) { s = ei32[2 * e]; d = ei32[2 * (E + e)]; }
    else        { s = ei32[e];     d = ei32[E + e]; }
    int pos = atomicAdd(&g_deg[d], 1);
    g_csrc[pos] = s;
}

// ---------------------------------------------------------------------------
// GEMM: C[N,128] = act(A[N,128]) @ W[128,128]  — f32x2 packed FMA
// Block 256 threads, 64-row tile. Warp = 8 rows, lane = 4 cols (2 u64 pairs).
// ---------------------------------------------------------------------------
template <bool RELU>
__global__ void gemm128_kernel(const float* __restrict__ A, const float* __restrict__ W,
                               float* __restrict__ C, int N) {
    extern __shared__ float sm[];
    float* Ws = sm;              // 128*128
    float* As = sm + 128 * 128;  // 64*128

    const int tid = threadIdx.x;

    // Load W (4096 float4)
    {
        const float4* W4 = (const float4*)W;
        float4* Ws4 = (float4*)Ws;
        #pragma unroll
        for (int i = 0; i < 16; i++) Ws4[tid + i * 256] = W4[tid + i * 256];
    }
    // Load A tile (64 rows x 32 float4)
    const int rowBase = blockIdx.x * 64;
    {
        const float4* A4 = (const float4*)A;
        float4* As4 = (float4*)As;
        #pragma unroll
        for (int i = 0; i < 8; i++) {
            int idx = tid + i * 256;
            int r = idx >> 5;
            int c4 = idx & 31;
            float4 v;
            if (rowBase + r < N) {
                v = A4[(size_t)(rowBase + r) * 32 + c4];
                if (RELU) {
                    v.x = fmaxf(v.x, 0.f); v.y = fmaxf(v.y, 0.f);
                    v.z = fmaxf(v.z, 0.f); v.w = fmaxf(v.w, 0.f);
                }
            } else {
                v = make_float4(0.f, 0.f, 0.f, 0.f);
            }
            As4[idx] = v;
        }
    }
    __syncthreads();

    const int lane = tid & 31;
    const int warp = tid >> 5;

    unsigned long long acc2[8][2];
    #pragma unroll
    for (int r = 0; r < 8; r++) { acc2[r][0] = 0ull; acc2[r][1] = 0ull; }

    for (int k = 0; k < 128; k += 4) {
        float4 a[8];
        #pragma unroll
        for (int r = 0; r < 8; r++)
            a[r] = *(const float4*)(As + (warp * 8 + r) * 128 + k);

        unsigned long long wlo[4], whi[4];
        #pragma unroll
        for (int kk = 0; kk < 4; kk++) {
            const unsigned long long* wp =
                (const unsigned long long*)(Ws + (k + kk) * 128 + lane * 4);
            wlo[kk] = wp[0];
            whi[kk] = wp[1];
        }

        #pragma unroll
        for (int kk = 0; kk < 4; kk++) {
            #pragma unroll
            for (int r = 0; r < 8; r++) {
                float av = (kk == 0) ? a[r].x : (kk == 1) ? a[r].y
                         : (kk == 2) ? a[r].z : a[r].w;
                unsigned long long av2 = pack2(av, av);
                FMA2(acc2[r][0], av2, wlo[kk]);
                FMA2(acc2[r][1], av2, whi[kk]);
            }
        }
    }

    #pragma unroll
    for (int r = 0; r < 8; r++) {
        int row = rowBase + warp * 8 + r;
        if (row < N) {
            float4 o;
            unpack2(o.x, o.y, acc2[r][0]);
            unpack2(o.z, o.w, acc2[r][1]);
            *(float4*)(C + (size_t)row * 128 + lane * 4) = o;
        }
    }
}

// ---------------------------------------------------------------------------
// GEMM: C[N,40] = relu(A[N,128]) @ W[128,40] — f32x2, one row per thread.
// ---------------------------------------------------------------------------
__global__ void gemm40_kernel(const float* __restrict__ A, const float* __restrict__ W,
                              float* __restrict__ C, int N) {
    __shared__ float Ws[128 * 40];
    for (int i = threadIdx.x; i < 128 * 40; i += blockDim.x) Ws[i] = W[i];
    __syncthreads();

    int row = blockIdx.x * blockDim.x + threadIdx.x;
    if (row >= N) return;

    unsigned long long acc2[20];
    #pragma unroll
    for (int j = 0; j < 20; j++) acc2[j] = 0ull;

    const float4* Arow = (const float4*)(A + (size_t)row * 128);
    for (int k4 = 0; k4 < 32; k4++) {
        float4 a = Arow[k4];
        a.x = fmaxf(a.x, 0.f); a.y = fmaxf(a.y, 0.f);
        a.z = fmaxf(a.z, 0.f); a.w = fmaxf(a.w, 0.f);
        #pragma unroll
        for (int kk = 0; kk < 4; kk++) {
            float av = (kk == 0) ? a.x : (kk == 1) ? a.y : (kk == 2) ? a.z : a.w;
            unsigned long long av2 = pack2(av, av);
            const unsigned long long* wrow =
                (const unsigned long long*)(Ws + (k4 * 4 + kk) * 40);
            #pragma unroll
            for (int j = 0; j < 20; j++) FMA2(acc2[j], av2, wrow[j]);
        }
    }

    unsigned long long* Co = (unsigned long long*)(C + (size_t)row * 40);
    #pragma unroll
    for (int j = 0; j < 20; j++) Co[j] = acc2[j];
}

// ---------------------------------------------------------------------------
// CSR gather (128 dims): one warp per node (node = base + warpIdx).
// agg[n] = b + sum_{e in csr[n]} hw[src[e]]
// ---------------------------------------------------------------------------
__global__ void gather128_kernel(const float* __restrict__ hw,
                                 const float* __restrict__ b,
                                 float* __restrict__ agg,
                                 int nodeBase, int nodeCount) {
    int wi = (blockIdx.x * blockDim.x + threadIdx.x) >> 5;
    int lane = threadIdx.x & 31;
    if (wi >= nodeCount) return;
    int w = nodeBase + wi;
    int beg = __ldg(&g_off[w]);
    int end = __ldg(&g_off[w + 1]);

    float4 acc = *(const float4*)(b + lane * 4);
    int i = beg;
    for (; i + 4 <= end; i += 4) {
        int s0 = g_csrc[i], s1 = g_csrc[i + 1], s2 = g_csrc[i + 2], s3 = g_csrc[i + 3];
        float4 v0 = *(const float4*)(hw + (size_t)s0 * 128 + lane * 4);
        float4 v1 = *(const float4*)(hw + (size_t)s1 * 128 + lane * 4);
        float4 v2 = *(const float4*)(hw + (size_t)s2 * 128 + lane * 4);
        float4 v3 = *(const float4*)(hw + (size_t)s3 * 128 + lane * 4);
        acc.x += v0.x + v1.x + v2.x + v3.x;
        acc.y += v0.y + v1.y + v2.y + v3.y;
        acc.z += v0.z + v1.z + v2.z + v3.z;
        acc.w += v0.w + v1.w + v2.w + v3.w;
    }
    for (; i < end; i++) {
        int s = g_csrc[i];
        float4 v = *(const float4*)(hw + (size_t)s * 128 + lane * 4);
        acc.x += v.x; acc.y += v.y; acc.z += v.z; acc.w += v.w;
    }
    *(float4*)(agg + (size_t)w * 128 + lane * 4) = acc;
}

// ---------------------------------------------------------------------------
// CSR gather (40 dims): one warp per node, lanes 0..9 own a float4 each.
// ---------------------------------------------------------------------------
__global__ void gather40_kernel(const float* __restrict__ hw,
                                const float* __restrict__ b,
                                float* __restrict__ out,
                                int nodeBase, int nodeCount) {
    int wi = (blockIdx.x * blockDim.x + threadIdx.x) >> 5;
    int lane = threadIdx.x & 31;
    if (wi >= nodeCount) return;
    int w = nodeBase + wi;
    int beg = __ldg(&g_off[w]);
    int end = __ldg(&g_off[w + 1]);

    float4 acc = make_float4(0.f, 0.f, 0.f, 0.f);
    if (lane < 10) acc = *(const float4*)(b + lane * 4);
    int i = beg;
    for (; i + 2 <= end; i += 2) {
        int s0 = g_csrc[i], s1 = g_csrc[i + 1];
        if (lane < 10) {
            float4 v0 = *(const float4*)(hw + (size_t)s0 * 40 + lane * 4);
            float4 v1 = *(const float4*)(hw + (size_t)s1 * 40 + lane * 4);
            acc.x += v0.x + v1.x; acc.y += v0.y + v1.y;
            acc.z += v0.z + v1.z; acc.w += v0.w + v1.w;
        }
    }
    for (; i < end; i++) {
        int s = g_csrc[i];
        if (lane < 10) {
            float4 v = *(const float4*)(hw + (size_t)s * 40 + lane * 4);
            acc.x += v.x; acc.y += v.y; acc.z += v.z; acc.w += v.w;
        }
    }
    if (lane < 10)
        *(float4*)(out + (size_t)w * 40 + lane * 4) = acc;
}

// ---------------------------------------------------------------------------
// Launch — CSR build overlapped with layer-0 GEMM; then half-split node
// pipeline across two streams. gemm(h) depends only on gather(h) of the SAME
// half (row-local); gathers depend on BOTH gemm halves (sources arbitrary).
// ---------------------------------------------------------------------------
extern "C" void kernel_launch(void* const* d_in, const int* in_sizes, int n_in,
                              void* d_out, int out_size) {
    const float* x  = (const float*)d_in[0];
    const int*   ei = (const int*)d_in[1];
    const float* W0 = (const float*)d_in[2];
    const float* b0 = (const float*)d_in[3];
    const float* W1 = (const float*)d_in[4];
    const float* b1 = (const float*)d_in[5];
    const float* W2 = (const float*)d_in[6];
    const float* b2 = (const float*)d_in[7];
    float* out = (float*)d_out;

    const int N = NUM_NODES, E = NUM_EDGES;

    float *bufHW, *bufAGG;
    cudaGetSymbolAddress((void**)&bufHW, g_bufHW);
    cudaGetSymbolAddress((void**)&bufAGG, g_bufAGG);
    int* degPtr;
    cudaGetSymbolAddress((void**)&degPtr, g_deg);

    const int SMEM = (128 * 128 + 64 * 128) * sizeof(float);  // 96KB
    cudaFuncSetAttribute(gemm128_kernel<false>, cudaFuncAttributeMaxDynamicSharedMemorySize, SMEM);
    cudaFuncSetAttribute(gemm128_kernel<true>,  cudaFuncAttributeMaxDynamicSharedMemorySize, SMEM);

    static cudaStream_t s1 = nullptr;
    static cudaEvent_t evFork = nullptr, evCSR = nullptr, evP0 = nullptr;
    static cudaEvent_t evG0 = nullptr, evG1 = nullptr;
    static cudaEvent_t evF0 = nullptr, evF1 = nullptr, evEnd = nullptr;
    if (s1 == nullptr) {
        cudaStreamCreateWithFlags(&s1, cudaStreamNonBlocking);
        cudaEventCreateWithFlags(&evFork, cudaEventDisableTiming);
        cudaEventCreateWithFlags(&evCSR,  cudaEventDisableTiming);
        cudaEventCreateWithFlags(&evP0,   cudaEventDisableTiming);
        cudaEventCreateWithFlags(&evG0,   cudaEventDisableTiming);
        cudaEventCreateWithFlags(&evG1,   cudaEventDisableTiming);
        cudaEventCreateWithFlags(&evF0,   cudaEventDisableTiming);
        cudaEventCreateWithFlags(&evF1,   cudaEventDisableTiming);
        cudaEventCreateWithFlags(&evEnd,  cudaEventDisableTiming);
    }

    // --- fork: CSR build on s1, layer-0 GEMM (full) on main ---
    cudaEventRecord(evFork, 0);
    cudaStreamWaitEvent(s1, evFork, 0);

    detect_idx_dtype<<<1, 32, 0, s1>>>(ei);
    cudaMemsetAsync(degPtr, 0, NUM_NODES * sizeof(int), s1);
    hist_kernel<<<(E + 255) / 256, 256, 0, s1>>>(ei, E);
    scanA_kernel<<<SCAN_NBLOCKS, SCAN_BLK, 0, s1>>>();
    scanB_kernel<<<1, 128, 0, s1>>>();
    scanC_kernel<<<(N + 255) / 256, 256, 0, s1>>>();
    fill_kernel<<<(E + 255) / 256, 256, 0, s1>>>(ei, E);
    cudaEventRecord(evCSR, s1);

    gemm128_kernel<false><<<(N + 63) / 64, 256, SMEM>>>(x, W0, bufHW, N);

    // --- join CSR, then fork the half-split pipeline ---
    cudaStreamWaitEvent(0, evCSR, 0);
    cudaEventRecord(evP0, 0);
    cudaStreamWaitEvent(s1, evP0, 0);

    const int GW0 = (HALF0 * 32 + 255) / 256;   // gather blocks, half 0
    const int GW1 = (HALF1 * 32 + 255) / 256;   // gather blocks, half 1
    const int GB0 = (HALF0 + 63) / 64;          // gemm128 blocks per half
    const int GB1 = (HALF1 + 63) / 64;

    float* hwH1  = bufHW  + (size_t)HALF0 * 128;
    float* aggH1 = bufAGG + (size_t)HALF0 * 128;

    // Stage: gather L0 (needs full gemm-L0 + CSR)
    gather128_kernel<<<GW0, 256, 0, 0 >>>(bufHW, b0, bufAGG, 0,     HALF0);
    gather128_kernel<<<GW1, 256, 0, s1>>>(bufHW, b0, bufAGG, HALF0, HALF1);

    // Stage: gemm L1 (own-half gather only)
    gemm128_kernel<true><<<GB0, 256, SMEM, 0 >>>(bufAGG, W1, bufHW, HALF0);
    cudaEventRecord(evG0, 0);
    gemm128_kernel<true><<<GB1, 256, SMEM, s1>>>(aggH1, W1, hwH1, HALF1);
    cudaEventRecord(evG1, s1);

    // Stage: gather L1 (needs BOTH gemm-L1 halves)
    cudaStreamWaitEvent(0, evG1, 0);
    cudaStreamWaitEvent(s1, evG0, 0);
    gather128_kernel<<<GW0, 256, 0, 0 >>>(bufHW, b1, bufAGG, 0,     HALF0);
    gather128_kernel<<<GW1, 256, 0, s1>>>(bufHW, b1, bufAGG, HALF0, HALF1);

    // Stage: gemm40 (own-half gather only); hw40 reuses bufHW (40 f/row)
    float* hw40H1 = bufHW + (size_t)HALF0 * 40;
    gemm40_kernel<<<(HALF0 + 255) / 256, 256, 0, 0 >>>(bufAGG, W2, bufHW, HALF0);
    cudaEventRecord(evF0, 0);
    gemm40_kernel<<<(HALF1 + 255) / 256, 256, 0, s1>>>(aggH1, W2, hw40H1, HALF1);
    cudaEventRecord(evF1, s1);

    // Stage: gather40 (needs BOTH gemm40 halves)
    cudaStreamWaitEvent(0, evF1, 0);
    cudaStreamWaitEvent(s1, evF0, 0);
    gather40_kernel<<<GW0, 256, 0, 0 >>>(bufHW, b2, out, 0,     HALF0);
    gather40_kernel<<<GW1, 256, 0, s1>>>(bufHW, b2, out, HALF0, HALF1);
    cudaEventRecord(evEnd, s1);
    cudaStreamWaitEvent(0, evEnd, 0);
}